// round 6
// baseline (speedup 1.0000x reference)
#include <cuda_runtime.h>
#include <cstdint>

#define N_POS   4096
#define HEADS   4
#define DHEAD   32
#define C_IN    256
#define HID     128          // HEADS*DHEAD
#define BATCH   4
#define SCALE   10.0f

// Scratch (no cudaMalloc allowed): qkv [b][3*128][n], attn-out [b][128][n]
__device__ float g_qkv[(size_t)BATCH * 3 * HID * N_POS];   // 25.2 MB
__device__ float g_att[(size_t)BATCH * HID * N_POS];       //  8.4 MB

// ---------------------------------------------------------------------------
// Generic tiled GEMM core: Y[b][o][i] = sum_c W[o][c] * X[b][c][i] (+ bias[o])
// ---------------------------------------------------------------------------
__device__ __forceinline__ void gemm_body(
    const float* __restrict__ W, const float* __restrict__ X,
    float* __restrict__ Y, const float* __restrict__ bias,
    int K, long xstride_b, long ystride_b)
{
    __shared__ float Ws[16][64];   // [c][o]
    __shared__ float Xs[16][64];   // [c][i]

    const int b  = blockIdx.z;
    const int o0 = blockIdx.y * 64;
    const int i0 = blockIdx.x * 64;
    const float* Xb = X + (long)b * xstride_b;
    float*       Yb = Y + (long)b * ystride_b;

    const int tid = threadIdx.x;
    const int ot  = tid >> 4;     // 0..15
    const int it  = tid & 15;     // 0..15

    float acc[4][4] = {};

    for (int k0 = 0; k0 < K; k0 += 16) {
        {
            int o = tid >> 2;                // 0..63
            int c = (tid & 3) * 4;           // 0,4,8,12
            float4 wv = *(const float4*)&W[(long)(o0 + o) * K + k0 + c];
            Ws[c + 0][o] = wv.x; Ws[c + 1][o] = wv.y;
            Ws[c + 2][o] = wv.z; Ws[c + 3][o] = wv.w;
        }
        {
            int c = tid >> 4;                // 0..15
            int i = (tid & 15) * 4;          // 0..60
            *(float4*)&Xs[c][i] =
                *(const float4*)&Xb[(long)(k0 + c) * N_POS + i0 + i];
        }
        __syncthreads();

        #pragma unroll
        for (int kk = 0; kk < 16; kk++) {
            float4 wv = *(const float4*)&Ws[kk][ot * 4];
            float4 xv = *(const float4*)&Xs[kk][it * 4];
            float a0 = wv.x, a1 = wv.y, a2 = wv.z, a3 = wv.w;
            acc[0][0] += a0 * xv.x; acc[0][1] += a0 * xv.y; acc[0][2] += a0 * xv.z; acc[0][3] += a0 * xv.w;
            acc[1][0] += a1 * xv.x; acc[1][1] += a1 * xv.y; acc[1][2] += a1 * xv.z; acc[1][3] += a1 * xv.w;
            acc[2][0] += a2 * xv.x; acc[2][1] += a2 * xv.y; acc[2][2] += a2 * xv.z; acc[2][3] += a2 * xv.w;
            acc[3][0] += a3 * xv.x; acc[3][1] += a3 * xv.y; acc[3][2] += a3 * xv.z; acc[3][3] += a3 * xv.w;
        }
        __syncthreads();
    }

    #pragma unroll
    for (int r = 0; r < 4; r++) {
        float bb = bias ? bias[o0 + ot * 4 + r] : 0.0f;
        float4 o4;
        o4.x = acc[r][0] + bb; o4.y = acc[r][1] + bb;
        o4.z = acc[r][2] + bb; o4.w = acc[r][3] + bb;
        *(float4*)&Yb[(long)(o0 + ot * 4 + r) * N_POS + i0 + it * 4] = o4;
    }
}

__global__ __launch_bounds__(256) void gemm_qkv_kernel(
    const float* __restrict__ W, const float* __restrict__ X)
{
    gemm_body(W, X, g_qkv, nullptr, C_IN,
              (long)C_IN * N_POS, (long)3 * HID * N_POS);
}

__global__ __launch_bounds__(256) void gemm_out_kernel(
    const float* __restrict__ W, float* __restrict__ Y,
    const float* __restrict__ bias)
{
    gemm_body(W, g_att, Y, bias, HID,
              (long)HID * N_POS, (long)C_IN * N_POS);
}

// ---------------------------------------------------------------------------
// L2-normalize q and k over the DHEAD axis, in place in g_qkv.
// ---------------------------------------------------------------------------
__global__ __launch_bounds__(256) void norm_kernel()
{
    int t = blockIdx.x * blockDim.x + threadIdx.x;
    int i = t & (N_POS - 1);
    int r = t >> 12;
    int h = r & 3;  r >>= 2;
    int s = r & 1;
    int b = r >> 1;

    float* base = g_qkv + ((long)(b * 3 + s) * HID + h * DHEAD) * N_POS + i;

    float v[DHEAD];
    float ss = 0.0f;
    #pragma unroll
    for (int d = 0; d < DHEAD; d++) {
        v[d] = base[(long)d * N_POS];
        ss += v[d] * v[d];
    }
    float inv = 1.0f / fmaxf(sqrtf(ss), 1e-12f);
    #pragma unroll
    for (int d = 0; d < DHEAD; d++)
        base[(long)d * N_POS] = v[d] * inv;
}

// ---------------------------------------------------------------------------
// Tensor-core flash attention, P kept in registers (no smem round-trip).
// Fixed softmax shift +10 (q,k unit => logits in [-10,10]): no online max.
//
// Block = (b, h, 64-query tile), 8 warps: warp (wq 0..3, wn 0..1).
//  GEMM1: warp computes S[16q x 32j] for j in [wn*32, wn*32+32)   (16 MMA)
//  P = exp(10S-10) in regs; quad shuffle-transpose c-frag -> a-frag
//  GEMM2: warp computes PARTIAL O[16q x 32d] over its own 32 k    (16 MMA)
//  Epilogue: wn=1 partials summed into wn=0 via smem, /l, store.
// Smem strides padded conflict-free: Qs/Ks 72, Vs 68.
// ---------------------------------------------------------------------------
#define QS_STR 72
#define KS_STR 72
#define VS_STR 68
#define OS_STR 68
#define PB_STR 33
#define FULLM  0xffffffffu

__device__ __forceinline__ uint32_t f2tf(float x) {
    uint32_t r;
    asm("cvt.rna.tf32.f32 %0, %1;" : "=r"(r) : "f"(x));
    return r;
}

__device__ __forceinline__ void mma_tf32(float d[4], const uint32_t a[4],
                                         const uint32_t b[2]) {
    asm volatile(
        "mma.sync.aligned.m16n8k8.row.col.f32.tf32.tf32.f32 "
        "{%0,%1,%2,%3}, {%4,%5,%6,%7}, {%8,%9}, {%0,%1,%2,%3};"
        : "+f"(d[0]), "+f"(d[1]), "+f"(d[2]), "+f"(d[3])
        : "r"(a[0]), "r"(a[1]), "r"(a[2]), "r"(a[3]), "r"(b[0]), "r"(b[1]));
}

// Within a quad (4 lanes, same q-row pair): regs hold cols 2*tig, 2*tig+1 of an
// 8-col group; return the value at column t (t = tig or tig+4 across lanes).
__device__ __forceinline__ float quad_col(float pe, float po, int srcTig, int parity) {
    float xe = __shfl_sync(FULLM, pe, srcTig, 4);
    float xo = __shfl_sync(FULLM, po, srcTig, 4);
    return parity ? xo : xe;
}

__global__ __launch_bounds__(256) void attn_tc_kernel()
{
    __shared__ uint32_t Qs[32 * QS_STR];     //  9.2 KB
    __shared__ uint32_t Ks[32 * KS_STR];     //  9.2 KB
    __shared__ uint32_t Vs[32 * VS_STR];     //  8.7 KB
    __shared__ float    Os[32 * OS_STR];     //  8.7 KB (epilogue only)
    __shared__ float    PB[64 * PB_STR];     //  8.4 KB (epilogue only)
    __shared__ float    sh_l[64];

    const int b   = blockIdx.z;
    const int h   = blockIdx.y;
    const int q0  = blockIdx.x * 64;
    const int tid = threadIdx.x;
    const int wid  = tid >> 5;
    const int lane = tid & 31;
    const int gid  = lane >> 2;   // 0..7
    const int tig  = lane & 3;    // 0..3

    const float* qb = g_qkv + ((long)(b * 3 + 0) * HID + h * DHEAD) * N_POS;
    const float* kb = g_qkv + ((long)(b * 3 + 1) * HID + h * DHEAD) * N_POS;
    const float* vb = g_qkv + ((long)(b * 3 + 2) * HID + h * DHEAD) * N_POS;

    // Load Q tile [32 d][64 q], rounded to tf32
    #pragma unroll
    for (int r = 0; r < 8; r++) {
        int idx = tid + r * 256;
        int d = idx >> 6, qi = idx & 63;
        Qs[d * QS_STR + qi] = f2tf(qb[(long)d * N_POS + q0 + qi]);
    }
    if (tid < 64) sh_l[tid] = 0.0f;

    const int wq = wid >> 1;   // 0..3 : 16-row q group
    const int wn = wid & 1;    // 0..1 : j/k half owned by this warp

    float O[4][4] = {};        // partial O[16q x 32d] over this warp's 32 k
    float l_lo = 0.0f, l_hi = 0.0f;

    for (int j0 = 0; j0 < N_POS; j0 += 64) {
        __syncthreads();   // previous-iter consumers of Ks/Vs done

        #pragma unroll
        for (int r = 0; r < 8; r++) {
            int idx = tid + r * 256;
            int d = idx >> 6, j = idx & 63;
            Ks[d * KS_STR + j] = f2tf(kb[(long)d * N_POS + j0 + j]);
            Vs[d * VS_STR + j] = f2tf(vb[(long)d * N_POS + j0 + j]);
        }
        __syncthreads();

        // ---- GEMM1: S[16 x 32] = Q K' (this warp's 32 j-cols) ----
        float S[4][4] = {};
        #pragma unroll
        for (int kk = 0; kk < 4; kk++) {
            uint32_t a[4];
            const int row = wq * 16 + gid;
            const int c0  = kk * 8 + tig;
            a[0] = Qs[c0 * QS_STR + row];
            a[1] = Qs[c0 * QS_STR + row + 8];
            a[2] = Qs[(c0 + 4) * QS_STR + row];
            a[3] = Qs[(c0 + 4) * QS_STR + row + 8];
            #pragma unroll
            for (int nt = 0; nt < 4; nt++) {
                const int col = wn * 32 + nt * 8 + gid;
                uint32_t bb[2];
                bb[0] = Ks[c0 * KS_STR + col];
                bb[1] = Ks[(c0 + 4) * KS_STR + col];
                mma_tf32(S[nt], a, bb);
            }
        }

        // ---- P = exp(10S - 10) in regs; accumulate l ----
        #pragma unroll
        for (int nt = 0; nt < 4; nt++) {
            S[nt][0] = __expf(fmaf(S[nt][0], SCALE, -SCALE));
            S[nt][1] = __expf(fmaf(S[nt][1], SCALE, -SCALE));
            S[nt][2] = __expf(fmaf(S[nt][2], SCALE, -SCALE));
            S[nt][3] = __expf(fmaf(S[nt][3], SCALE, -SCALE));
            l_lo += S[nt][0] + S[nt][1];
            l_hi += S[nt][2] + S[nt][3];
        }

        // ---- GEMM2: O += P[16 x 32] V'[32 x 32] (this warp's k-half) ----
        const int srcA = tig >> 1;
        const int srcB = srcA + 2;
        const int par  = tig & 1;
        #pragma unroll
        for (int nt = 0; nt < 4; nt++) {   // k-step over this warp's 8-col groups
            uint32_t a[4];
            // c-frag (cols 2tig,2tig+1) -> a-frag (cols tig, tig+4), per row-half
            a[0] = f2tf(quad_col(S[nt][0], S[nt][1], srcA, par));   // (gid,   tig)
            a[1] = f2tf(quad_col(S[nt][2], S[nt][3], srcA, par));   // (gid+8, tig)
            a[2] = f2tf(quad_col(S[nt][0], S[nt][1], srcB, par));   // (gid,   tig+4)
            a[3] = f2tf(quad_col(S[nt][2], S[nt][3], srcB, par));   // (gid+8, tig+4)
            const int kbase = wn * 32 + nt * 8;
            #pragma unroll
            for (int dt = 0; dt < 4; dt++) {
                const int dcol = dt * 8 + gid;
                uint32_t bb[2];
                bb[0] = Vs[dcol * VS_STR + kbase + tig];
                bb[1] = Vs[dcol * VS_STR + kbase + tig + 4];
                mma_tf32(O[dt], a, bb);
            }
        }
    }

    // ---- reduce l: quad shuffles, then across warps via shared atomics ----
    l_lo += __shfl_xor_sync(FULLM, l_lo, 1);
    l_lo += __shfl_xor_sync(FULLM, l_lo, 2);
    l_hi += __shfl_xor_sync(FULLM, l_hi, 1);
    l_hi += __shfl_xor_sync(FULLM, l_hi, 2);
    if (tig == 0) {
        atomicAdd(&sh_l[wq * 16 + gid],     l_lo);
        atomicAdd(&sh_l[wq * 16 + gid + 8], l_hi);
    }
    __syncthreads();

    const float invl_lo = 1.0f / sh_l[wq * 16 + gid];
    const float invl_hi = 1.0f / sh_l[wq * 16 + gid + 8];

    // ---- merge k-half partials: wn=1 stages, wn=0 sums + normalizes ----
    if (wn == 1) {
        #pragma unroll
        for (int nt = 0; nt < 4; nt++) {
            const int row = wq * 16 + gid;
            const int col = nt * 8 + 2 * tig;
            PB[row * PB_STR + col]           = O[nt][0];
            PB[row * PB_STR + col + 1]       = O[nt][1];
            PB[(row + 8) * PB_STR + col]     = O[nt][2];
            PB[(row + 8) * PB_STR + col + 1] = O[nt][3];
        }
    }
    __syncthreads();
    if (wn == 0) {
        #pragma unroll
        for (int nt = 0; nt < 4; nt++) {
            const int row = wq * 16 + gid;
            const int col = nt * 8 + 2 * tig;   // d-column
            float o0 = (O[nt][0] + PB[row * PB_STR + col])           * invl_lo;
            float o1 = (O[nt][1] + PB[row * PB_STR + col + 1])       * invl_lo;
            float o2 = (O[nt][2] + PB[(row + 8) * PB_STR + col])     * invl_hi;
            float o3 = (O[nt][3] + PB[(row + 8) * PB_STR + col + 1]) * invl_hi;
            Os[col * OS_STR + row]           = o0;
            Os[(col + 1) * OS_STR + row]     = o1;
            Os[col * OS_STR + row + 8]       = o2;
            Os[(col + 1) * OS_STR + row + 8] = o3;
        }
    }
    __syncthreads();

    float* ob = g_att + ((long)b * HID + h * DHEAD) * N_POS + q0;
    #pragma unroll
    for (int r = 0; r < 8; r++) {
        int idx = tid + r * 256;
        int d = idx >> 6, qi = idx & 63;
        ob[(long)d * N_POS + qi] = Os[d * OS_STR + qi];
    }
}

// ---------------------------------------------------------------------------
extern "C" void kernel_launch(void* const* d_in, const int* in_sizes, int n_in,
                              void* d_out, int out_size)
{
    const float* x     = (const float*)d_in[0];   // [4,256,64,64]
    const float* w_qkv = (const float*)d_in[1];   // [384,256]
    const float* w_out = (const float*)d_in[2];   // [256,128]
    const float* b_out = (const float*)d_in[3];   // [256]
    float* y = (float*)d_out;                     // [4,256,64,64]

    // A: qkv = w_qkv @ x
    {
        dim3 grid(N_POS / 64, (3 * HID) / 64, BATCH);
        gemm_qkv_kernel<<<grid, 256>>>(w_qkv, x);
    }
    // B: L2-normalize q, k
    {
        int total = 2 * BATCH * HEADS * N_POS;
        norm_kernel<<<total / 256, 256>>>();
    }
    // C: tensor-core flash attention
    {
        dim3 grid(N_POS / 64, HEADS, BATCH);
        attn_tc_kernel<<<grid, 256>>>();
    }
    // D: y = w_out @ att + b_out
    {
        dim3 grid(N_POS / 64, C_IN / 64, BATCH);
        gemm_out_kernel<<<grid, 256>>>(w_out, y, b_out);
    }
}

// round 8
// speedup vs baseline: 1.1994x; 1.1994x over previous
#include <cuda_runtime.h>
#include <cstdint>

#define N_POS   4096
#define HEADS   4
#define DHEAD   32
#define C_IN    256
#define HID     128          // HEADS*DHEAD
#define BATCH   4
#define SCALE   10.0f

// Scratch (no cudaMalloc allowed): qkv [b][3*128][n], attn-out [b][128][n]
__device__ float g_qkv[(size_t)BATCH * 3 * HID * N_POS];   // 25.2 MB
__device__ float g_att[(size_t)BATCH * HID * N_POS];       //  8.4 MB

#define FULLM  0xffffffffu

__device__ __forceinline__ uint32_t f2tf(float x) {
    uint32_t r;
    asm("cvt.rna.tf32.f32 %0, %1;" : "=r"(r) : "f"(x));
    return r;
}

__device__ __forceinline__ void mma_tf32(float d[4], const uint32_t a[4],
                                         const uint32_t b[2]) {
    asm volatile(
        "mma.sync.aligned.m16n8k8.row.col.f32.tf32.tf32.f32 "
        "{%0,%1,%2,%3}, {%4,%5,%6,%7}, {%8,%9}, {%0,%1,%2,%3};"
        : "+f"(d[0]), "+f"(d[1]), "+f"(d[2]), "+f"(d[3])
        : "r"(a[0]), "r"(a[1]), "r"(a[2]), "r"(a[3]), "r"(b[0]), "r"(b[1]));
}

// ---------------------------------------------------------------------------
// Tensor-core projection GEMM with 3-term tf32 split (fp32-level accuracy):
//   Y[b][o][i] = sum_c W[o][c] X[b][c][i] (+ bias[o])
//   W = Wh+Wl, X = Xh+Xl ; acc += Wh*Xh + Wh*Xl + Wl*Xh
// Block 256 thr = 8 warps, out tile 64(o) x 64(i); warp tile 16(o) x 32(i).
// k-tile 16. Fragment banks: Ws stride 20 -> 20*gid+tig distinct;
// Xs stride 72 -> 8*tig+gid distinct.
// ---------------------------------------------------------------------------
#define WS_STR 20
#define XS_STR 72

__device__ __forceinline__ void gemm_tc_body(
    const float* __restrict__ W, const float* __restrict__ X,
    float* __restrict__ Y, const float* __restrict__ bias,
    int K, long xstride_b, long ystride_b)
{
    __shared__ uint32_t WsH[64 * WS_STR], WsL[64 * WS_STR];
    __shared__ uint32_t XsH[16 * XS_STR], XsL[16 * XS_STR];

    const int b  = blockIdx.z;
    const int o0 = blockIdx.y * 64;
    const int i0 = blockIdx.x * 64;
    const float* Xb = X + (long)b * xstride_b;
    float*       Yb = Y + (long)b * ystride_b;

    const int tid  = threadIdx.x;
    const int wid  = tid >> 5;
    const int lane = tid & 31;
    const int gid  = lane >> 2;
    const int tig  = lane & 3;
    const int wq   = wid >> 1;   // o-quarter
    const int wn   = wid & 1;    // i-half

    float acc[4][4] = {};

    for (int k0 = 0; k0 < K; k0 += 16) {
        __syncthreads();
        // stage W tile [64 o][16 c], split hi/lo, layout [o][c]
        {
            int o  = tid >> 2;
            int c4 = (tid & 3) * 4;
            float4 wv = *(const float4*)&W[(long)(o0 + o) * K + k0 + c4];
            uint4 h, l;
            h.x = f2tf(wv.x); l.x = f2tf(wv.x - __uint_as_float(h.x));
            h.y = f2tf(wv.y); l.y = f2tf(wv.y - __uint_as_float(h.y));
            h.z = f2tf(wv.z); l.z = f2tf(wv.z - __uint_as_float(h.z));
            h.w = f2tf(wv.w); l.w = f2tf(wv.w - __uint_as_float(h.w));
            *(uint4*)&WsH[o * WS_STR + c4] = h;
            *(uint4*)&WsL[o * WS_STR + c4] = l;
        }
        // stage X tile [16 c][64 i], split hi/lo, layout [c][i]
        {
            int c  = tid >> 4;
            int i4 = (tid & 15) * 4;
            float4 xv = *(const float4*)&Xb[(long)(k0 + c) * N_POS + i0 + i4];
            uint4 h, l;
            h.x = f2tf(xv.x); l.x = f2tf(xv.x - __uint_as_float(h.x));
            h.y = f2tf(xv.y); l.y = f2tf(xv.y - __uint_as_float(h.y));
            h.z = f2tf(xv.z); l.z = f2tf(xv.z - __uint_as_float(h.z));
            h.w = f2tf(xv.w); l.w = f2tf(xv.w - __uint_as_float(h.w));
            *(uint4*)&XsH[c * XS_STR + i4] = h;
            *(uint4*)&XsL[c * XS_STR + i4] = l;
        }
        __syncthreads();

        #pragma unroll
        for (int kk = 0; kk < 2; kk++) {
            const int ar = wq * 16 + gid;
            const int ac = kk * 8 + tig;
            uint32_t aH[4], aL[4];
            aH[0] = WsH[ar * WS_STR + ac];
            aH[1] = WsH[(ar + 8) * WS_STR + ac];
            aH[2] = WsH[ar * WS_STR + ac + 4];
            aH[3] = WsH[(ar + 8) * WS_STR + ac + 4];
            aL[0] = WsL[ar * WS_STR + ac];
            aL[1] = WsL[(ar + 8) * WS_STR + ac];
            aL[2] = WsL[ar * WS_STR + ac + 4];
            aL[3] = WsL[(ar + 8) * WS_STR + ac + 4];
            #pragma unroll
            for (int nt = 0; nt < 4; nt++) {
                const int col = wn * 32 + nt * 8 + gid;
                const int cr  = kk * 8 + tig;
                uint32_t bH[2], bL[2];
                bH[0] = XsH[cr * XS_STR + col];
                bH[1] = XsH[(cr + 4) * XS_STR + col];
                bL[0] = XsL[cr * XS_STR + col];
                bL[1] = XsL[(cr + 4) * XS_STR + col];
                mma_tf32(acc[nt], aH, bH);
                mma_tf32(acc[nt], aH, bL);
                mma_tf32(acc[nt], aL, bH);
            }
        }
    }

    // epilogue: c-frag (row gid/gid+8, cols 2tig,2tig+1) -> direct STG.64
    const int orow = o0 + wq * 16 + gid;
    const float b0 = bias ? bias[orow]     : 0.0f;
    const float b1 = bias ? bias[orow + 8] : 0.0f;
    #pragma unroll
    for (int nt = 0; nt < 4; nt++) {
        const int col = i0 + wn * 32 + nt * 8 + 2 * tig;
        float2 lo, hi;
        lo.x = acc[nt][0] + b0; lo.y = acc[nt][1] + b0;
        hi.x = acc[nt][2] + b1; hi.y = acc[nt][3] + b1;
        *(float2*)&Yb[(long)orow * N_POS + col]       = lo;
        *(float2*)&Yb[(long)(orow + 8) * N_POS + col] = hi;
    }
}

__global__ __launch_bounds__(256) void gemm_qkv_kernel(
    const float* __restrict__ W, const float* __restrict__ X)
{
    gemm_tc_body(W, X, g_qkv, nullptr, C_IN,
                 (long)C_IN * N_POS, (long)3 * HID * N_POS);
}

__global__ __launch_bounds__(256) void gemm_out_kernel(
    const float* __restrict__ W, float* __restrict__ Y,
    const float* __restrict__ bias)
{
    gemm_tc_body(W, g_att, Y, bias, HID,
                 (long)HID * N_POS, (long)C_IN * N_POS);
}

// ---------------------------------------------------------------------------
// L2-normalize q and k over the DHEAD axis, in place in g_qkv.
// ---------------------------------------------------------------------------
__global__ __launch_bounds__(256) void norm_kernel()
{
    int t = blockIdx.x * blockDim.x + threadIdx.x;
    int i = t & (N_POS - 1);
    int r = t >> 12;
    int h = r & 3;  r >>= 2;
    int s = r & 1;
    int b = r >> 1;

    float* base = g_qkv + ((long)(b * 3 + s) * HID + h * DHEAD) * N_POS + i;

    float v[DHEAD];
    float ss = 0.0f;
    #pragma unroll
    for (int d = 0; d < DHEAD; d++) {
        v[d] = base[(long)d * N_POS];
        ss += v[d] * v[d];
    }
    float inv = 1.0f / fmaxf(sqrtf(ss), 1e-12f);
    #pragma unroll
    for (int d = 0; d < DHEAD; d++)
        base[(long)d * N_POS] = v[d] * inv;
}

// ---------------------------------------------------------------------------
// Tensor-core flash attention, P in registers, K/V register-prefetch
// double buffering (next tile's LDGs in flight during current tile's MMAs).
// Fixed softmax shift +10 (q,k unit => logits in [-10,10]): no online max.
// ---------------------------------------------------------------------------
#define QS_STR 72
#define KS_STR 72
#define VS_STR 68
#define OS_STR 68
#define PB_STR 33

__device__ __forceinline__ float quad_col(float pe, float po, int srcTig, int parity) {
    float xe = __shfl_sync(FULLM, pe, srcTig, 4);
    float xo = __shfl_sync(FULLM, po, srcTig, 4);
    return parity ? xo : xe;
}

__global__ __launch_bounds__(256, 2) void attn_tc_kernel()
{
    __shared__ uint32_t Qs[32 * QS_STR];
    __shared__ uint32_t Ks[32 * KS_STR];
    __shared__ uint32_t Vs[32 * VS_STR];
    __shared__ float    Os[32 * OS_STR];     // epilogue only
    __shared__ float    PB[64 * PB_STR];     // epilogue only
    __shared__ float    sh_l[64];

    const int b   = blockIdx.z;
    const int h   = blockIdx.y;
    const int q0  = blockIdx.x * 64;
    const int tid = threadIdx.x;
    const int wid  = tid >> 5;
    const int lane = tid & 31;
    const int gid  = lane >> 2;
    const int tig  = lane & 3;

    const float* qb = g_qkv + ((long)(b * 3 + 0) * HID + h * DHEAD) * N_POS;
    const float* kb = g_qkv + ((long)(b * 3 + 1) * HID + h * DHEAD) * N_POS;
    const float* vb = g_qkv + ((long)(b * 3 + 2) * HID + h * DHEAD) * N_POS;

    // Load Q tile [32 d][64 q], rounded to tf32
    #pragma unroll
    for (int r = 0; r < 8; r++) {
        int idx = tid + r * 256;
        int d = idx >> 6, qi = idx & 63;
        Qs[d * QS_STR + qi] = f2tf(qb[(long)d * N_POS + q0 + qi]);
    }
    if (tid < 64) sh_l[tid] = 0.0f;

    const int wq = wid >> 1;
    const int wn = wid & 1;

    float O[4][4] = {};
    float l_lo = 0.0f, l_hi = 0.0f;

    // prefetch tile 0 into registers
    float kreg[8], vreg[8];
    #pragma unroll
    for (int r = 0; r < 8; r++) {
        int idx = tid + r * 256;
        int d = idx >> 6, j = idx & 63;
        kreg[r] = kb[(long)d * N_POS + j];
        vreg[r] = vb[(long)d * N_POS + j];
    }

    for (int j0 = 0; j0 < N_POS; j0 += 64) {
        __syncthreads();   // previous-iter consumers of Ks/Vs done (+ Q/sh_l fence)

        #pragma unroll
        for (int r = 0; r < 8; r++) {
            int idx = tid + r * 256;
            int d = idx >> 6, j = idx & 63;
            Ks[d * KS_STR + j] = f2tf(kreg[r]);
            Vs[d * VS_STR + j] = f2tf(vreg[r]);
        }
        __syncthreads();

        // issue next tile's global loads (hidden under the MMAs below)
        if (j0 + 64 < N_POS) {
            #pragma unroll
            for (int r = 0; r < 8; r++) {
                int idx = tid + r * 256;
                int d = idx >> 6, j = idx & 63;
                kreg[r] = kb[(long)d * N_POS + j0 + 64 + j];
                vreg[r] = vb[(long)d * N_POS + j0 + 64 + j];
            }
        }

        // ---- GEMM1: S[16 x 32] = Q K' (this warp's 32 j-cols) ----
        float S[4][4] = {};
        #pragma unroll
        for (int kk = 0; kk < 4; kk++) {
            uint32_t a[4];
            const int row = wq * 16 + gid;
            const int c0  = kk * 8 + tig;
            a[0] = Qs[c0 * QS_STR + row];
            a[1] = Qs[c0 * QS_STR + row + 8];
            a[2] = Qs[(c0 + 4) * QS_STR + row];
            a[3] = Qs[(c0 + 4) * QS_STR + row + 8];
            #pragma unroll
            for (int nt = 0; nt < 4; nt++) {
                const int col = wn * 32 + nt * 8 + gid;
                uint32_t bb[2];
                bb[0] = Ks[c0 * KS_STR + col];
                bb[1] = Ks[(c0 + 4) * KS_STR + col];
                mma_tf32(S[nt], a, bb);
            }
        }

        // ---- P = exp(10S - 10) in regs; accumulate l ----
        #pragma unroll
        for (int nt = 0; nt < 4; nt++) {
            S[nt][0] = __expf(fmaf(S[nt][0], SCALE, -SCALE));
            S[nt][1] = __expf(fmaf(S[nt][1], SCALE, -SCALE));
            S[nt][2] = __expf(fmaf(S[nt][2], SCALE, -SCALE));
            S[nt][3] = __expf(fmaf(S[nt][3], SCALE, -SCALE));
            l_lo += S[nt][0] + S[nt][1];
            l_hi += S[nt][2] + S[nt][3];
        }

        // ---- GEMM2: O += P[16 x 32] V'[32 x 32] (this warp's k-half) ----
        const int srcA = tig >> 1;
        const int srcB = srcA + 2;
        const int par  = tig & 1;
        #pragma unroll
        for (int nt = 0; nt < 4; nt++) {
            uint32_t a[4];
            a[0] = f2tf(quad_col(S[nt][0], S[nt][1], srcA, par));
            a[1] = f2tf(quad_col(S[nt][2], S[nt][3], srcA, par));
            a[2] = f2tf(quad_col(S[nt][0], S[nt][1], srcB, par));
            a[3] = f2tf(quad_col(S[nt][2], S[nt][3], srcB, par));
            const int kbase = wn * 32 + nt * 8;
            #pragma unroll
            for (int dt = 0; dt < 4; dt++) {
                const int dcol = dt * 8 + gid;
                uint32_t bb[2];
                bb[0] = Vs[dcol * VS_STR + kbase + tig];
                bb[1] = Vs[dcol * VS_STR + kbase + tig + 4];
                mma_tf32(O[dt], a, bb);
            }
        }
    }

    // ---- reduce l: quad shuffles, then across warps via shared atomics ----
    l_lo += __shfl_xor_sync(FULLM, l_lo, 1);
    l_lo += __shfl_xor_sync(FULLM, l_lo, 2);
    l_hi += __shfl_xor_sync(FULLM, l_hi, 1);
    l_hi += __shfl_xor_sync(FULLM, l_hi, 2);
    if (tig == 0) {
        atomicAdd(&sh_l[wq * 16 + gid],     l_lo);
        atomicAdd(&sh_l[wq * 16 + gid + 8], l_hi);
    }
    __syncthreads();

    const float invl_lo = 1.0f / sh_l[wq * 16 + gid];
    const float invl_hi = 1.0f / sh_l[wq * 16 + gid + 8];

    // ---- merge k-half partials: wn=1 stages, wn=0 sums + normalizes ----
    if (wn == 1) {
        #pragma unroll
        for (int nt = 0; nt < 4; nt++) {
            const int row = wq * 16 + gid;
            const int col = nt * 8 + 2 * tig;
            PB[row * PB_STR + col]           = O[nt][0];
            PB[row * PB_STR + col + 1]       = O[nt][1];
            PB[(row + 8) * PB_STR + col]     = O[nt][2];
            PB[(row + 8) * PB_STR + col + 1] = O[nt][3];
        }
    }
    __syncthreads();
    if (wn == 0) {
        #pragma unroll
        for (int nt = 0; nt < 4; nt++) {
            const int row = wq * 16 + gid;
            const int col = nt * 8 + 2 * tig;
            float o0 = (O[nt][0] + PB[row * PB_STR + col])           * invl_lo;
            float o1 = (O[nt][1] + PB[row * PB_STR + col + 1])       * invl_lo;
            float o2 = (O[nt][2] + PB[(row + 8) * PB_STR + col])     * invl_hi;
            float o3 = (O[nt][3] + PB[(row + 8) * PB_STR + col + 1]) * invl_hi;
            Os[col * OS_STR + row]           = o0;
            Os[(col + 1) * OS_STR + row]     = o1;
            Os[col * OS_STR + row + 8]       = o2;
            Os[(col + 1) * OS_STR + row + 8] = o3;
        }
    }
    __syncthreads();

    float* ob = g_att + ((long)b * HID + h * DHEAD) * N_POS + q0;
    #pragma unroll
    for (int r = 0; r < 8; r++) {
        int idx = tid + r * 256;
        int d = idx >> 6, qi = idx & 63;
        ob[(long)d * N_POS + qi] = Os[d * OS_STR + qi];
    }
}

// ---------------------------------------------------------------------------
extern "C" void kernel_launch(void* const* d_in, const int* in_sizes, int n_in,
                              void* d_out, int out_size)
{
    const float* x     = (const float*)d_in[0];   // [4,256,64,64]
    const float* w_qkv = (const float*)d_in[1];   // [384,256]
    const float* w_out = (const float*)d_in[2];   // [256,128]
    const float* b_out = (const float*)d_in[3];   // [256]
    float* y = (float*)d_out;                     // [4,256,64,64]

    // A: qkv = w_qkv @ x   (tf32 split MMA)
    {
        dim3 grid(N_POS / 64, (3 * HID) / 64, BATCH);
        gemm_qkv_kernel<<<grid, 256>>>(w_qkv, x);
    }
    // B: L2-normalize q, k
    {
        int total = 2 * BATCH * HEADS * N_POS;
        norm_kernel<<<total / 256, 256>>>();
    }
    // C: tensor-core flash attention
    {
        dim3 grid(N_POS / 64, HEADS, BATCH);
        attn_tc_kernel<<<grid, 256>>>();
    }
    // D: y = w_out @ att + b_out   (tf32 split MMA)
    {
        dim3 grid(N_POS / 64, C_IN / 64, BATCH);
        gemm_out_kernel<<<grid, 256>>>(w_out, y, b_out);
    }
}

// round 9
// speedup vs baseline: 1.3796x; 1.1502x over previous
#include <cuda_runtime.h>
#include <cstdint>

#define N_POS   4096
#define HEADS   4
#define DHEAD   32
#define C_IN    256
#define HID     128          // HEADS*DHEAD
#define BATCH   4
#define SCALE   10.0f

// Scratch (no cudaMalloc allowed): qkv [b][3*128][n], attn-out [b][128][n]
__device__ float g_qkv[(size_t)BATCH * 3 * HID * N_POS];   // 25.2 MB
__device__ float g_att[(size_t)BATCH * HID * N_POS];       //  8.4 MB

#define FULLM  0xffffffffu

__device__ __forceinline__ uint32_t f2tf(float x) {
    uint32_t r;
    asm("cvt.rna.tf32.f32 %0, %1;" : "=r"(r) : "f"(x));
    return r;
}

__device__ __forceinline__ void mma_tf32(float d[4], const uint32_t a[4],
                                         const uint32_t b[2]) {
    asm volatile(
        "mma.sync.aligned.m16n8k8.row.col.f32.tf32.tf32.f32 "
        "{%0,%1,%2,%3}, {%4,%5,%6,%7}, {%8,%9}, {%0,%1,%2,%3};"
        : "+f"(d[0]), "+f"(d[1]), "+f"(d[2]), "+f"(d[3])
        : "r"(a[0]), "r"(a[1]), "r"(a[2]), "r"(a[3]), "r"(b[0]), "r"(b[1]));
}

__device__ __forceinline__ void cp_async16(void* smem_dst, const void* gsrc) {
    uint32_t s = (uint32_t)__cvta_generic_to_shared(smem_dst);
    asm volatile("cp.async.cg.shared.global [%0], [%1], 16;\n"
                 :: "r"(s), "l"(gsrc) : "memory");
}

// ---------------------------------------------------------------------------
// Tensor-core projection GEMM with 3-term tf32 split (fp32-level accuracy).
// ---------------------------------------------------------------------------
#define WS_STR 20
#define XS_STR 72

__device__ __forceinline__ void gemm_tc_body(
    const float* __restrict__ W, const float* __restrict__ X,
    float* __restrict__ Y, const float* __restrict__ bias,
    int K, long xstride_b, long ystride_b)
{
    __shared__ uint32_t WsH[64 * WS_STR], WsL[64 * WS_STR];
    __shared__ uint32_t XsH[16 * XS_STR], XsL[16 * XS_STR];

    const int b  = blockIdx.z;
    const int o0 = blockIdx.y * 64;
    const int i0 = blockIdx.x * 64;
    const float* Xb = X + (long)b * xstride_b;
    float*       Yb = Y + (long)b * ystride_b;

    const int tid  = threadIdx.x;
    const int wid  = tid >> 5;
    const int lane = tid & 31;
    const int gid  = lane >> 2;
    const int tig  = lane & 3;
    const int wq   = wid >> 1;
    const int wn   = wid & 1;

    float acc[4][4] = {};

    for (int k0 = 0; k0 < K; k0 += 16) {
        __syncthreads();
        {
            int o  = tid >> 2;
            int c4 = (tid & 3) * 4;
            float4 wv = *(const float4*)&W[(long)(o0 + o) * K + k0 + c4];
            uint4 h, l;
            h.x = f2tf(wv.x); l.x = f2tf(wv.x - __uint_as_float(h.x));
            h.y = f2tf(wv.y); l.y = f2tf(wv.y - __uint_as_float(h.y));
            h.z = f2tf(wv.z); l.z = f2tf(wv.z - __uint_as_float(h.z));
            h.w = f2tf(wv.w); l.w = f2tf(wv.w - __uint_as_float(h.w));
            *(uint4*)&WsH[o * WS_STR + c4] = h;
            *(uint4*)&WsL[o * WS_STR + c4] = l;
        }
        {
            int c  = tid >> 4;
            int i4 = (tid & 15) * 4;
            float4 xv = *(const float4*)&Xb[(long)(k0 + c) * N_POS + i0 + i4];
            uint4 h, l;
            h.x = f2tf(xv.x); l.x = f2tf(xv.x - __uint_as_float(h.x));
            h.y = f2tf(xv.y); l.y = f2tf(xv.y - __uint_as_float(h.y));
            h.z = f2tf(xv.z); l.z = f2tf(xv.z - __uint_as_float(h.z));
            h.w = f2tf(xv.w); l.w = f2tf(xv.w - __uint_as_float(h.w));
            *(uint4*)&XsH[c * XS_STR + i4] = h;
            *(uint4*)&XsL[c * XS_STR + i4] = l;
        }
        __syncthreads();

        #pragma unroll
        for (int kk = 0; kk < 2; kk++) {
            const int ar = wq * 16 + gid;
            const int ac = kk * 8 + tig;
            uint32_t aH[4], aL[4];
            aH[0] = WsH[ar * WS_STR + ac];
            aH[1] = WsH[(ar + 8) * WS_STR + ac];
            aH[2] = WsH[ar * WS_STR + ac + 4];
            aH[3] = WsH[(ar + 8) * WS_STR + ac + 4];
            aL[0] = WsL[ar * WS_STR + ac];
            aL[1] = WsL[(ar + 8) * WS_STR + ac];
            aL[2] = WsL[ar * WS_STR + ac + 4];
            aL[3] = WsL[(ar + 8) * WS_STR + ac + 4];
            #pragma unroll
            for (int nt = 0; nt < 4; nt++) {
                const int col = wn * 32 + nt * 8 + gid;
                const int cr  = kk * 8 + tig;
                uint32_t bH[2], bL[2];
                bH[0] = XsH[cr * XS_STR + col];
                bH[1] = XsH[(cr + 4) * XS_STR + col];
                bL[0] = XsL[cr * XS_STR + col];
                bL[1] = XsL[(cr + 4) * XS_STR + col];
                mma_tf32(acc[nt], aH, bH);
                mma_tf32(acc[nt], aH, bL);
                mma_tf32(acc[nt], aL, bH);
            }
        }
    }

    const int orow = o0 + wq * 16 + gid;
    const float b0 = bias ? bias[orow]     : 0.0f;
    const float b1 = bias ? bias[orow + 8] : 0.0f;
    #pragma unroll
    for (int nt = 0; nt < 4; nt++) {
        const int col = i0 + wn * 32 + nt * 8 + 2 * tig;
        float2 lo, hi;
        lo.x = acc[nt][0] + b0; lo.y = acc[nt][1] + b0;
        hi.x = acc[nt][2] + b1; hi.y = acc[nt][3] + b1;
        *(float2*)&Yb[(long)orow * N_POS + col]       = lo;
        *(float2*)&Yb[(long)(orow + 8) * N_POS + col] = hi;
    }
}

__global__ __launch_bounds__(256) void gemm_qkv_kernel(
    const float* __restrict__ W, const float* __restrict__ X)
{
    gemm_tc_body(W, X, g_qkv, nullptr, C_IN,
                 (long)C_IN * N_POS, (long)3 * HID * N_POS);
}

__global__ __launch_bounds__(256) void gemm_out_kernel(
    const float* __restrict__ W, float* __restrict__ Y,
    const float* __restrict__ bias)
{
    gemm_tc_body(W, g_att, Y, bias, HID,
                 (long)HID * N_POS, (long)C_IN * N_POS);
}

// ---------------------------------------------------------------------------
// L2-normalize q and k over the DHEAD axis, in place in g_qkv.
// ---------------------------------------------------------------------------
__global__ __launch_bounds__(256) void norm_kernel()
{
    int t = blockIdx.x * blockDim.x + threadIdx.x;
    int i = t & (N_POS - 1);
    int r = t >> 12;
    int h = r & 3;  r >>= 2;
    int s = r & 1;
    int b = r >> 1;

    float* base = g_qkv + ((long)(b * 3 + s) * HID + h * DHEAD) * N_POS + i;

    float v[DHEAD];
    float ss = 0.0f;
    #pragma unroll
    for (int d = 0; d < DHEAD; d++) {
        v[d] = base[(long)d * N_POS];
        ss += v[d] * v[d];
    }
    float inv = 1.0f / fmaxf(sqrtf(ss), 1e-12f);
    #pragma unroll
    for (int d = 0; d < DHEAD; d++)
        base[(long)d * N_POS] = v[d] * inv;
}

// ---------------------------------------------------------------------------
// Tensor-core flash attention, q-tile 128:
//  - Q fragments entirely in registers (loaded once, zero smem traffic)
//  - K/V staged fp32 via 2-stage cp.async ring (no staging regs, no STS)
//  - each warp: 32 q-rows x 32 j-cols -> every b-frag LDS feeds 2 MMAs
//  - fixed softmax shift +10, P in regs via quad shuffle-transpose
// Block = (b, h, 128-query tile), 8 warps (wq 0..3 x wn 0..1), 512 blocks.
// ---------------------------------------------------------------------------
#define KS_STR 72     // 72 % 32 == 8 -> b-frag bank = 8*tig+gid, distinct
#define VS_STR 68     // 68 % 32 == 4 -> b-frag bank = 4*gid+tig, distinct
#define OS_STR 136
#define PB_STR 33
#define STG_WORDS (32 * KS_STR + 32 * VS_STR)   // 4480 floats per stage

__device__ __forceinline__ float quad_col(float pe, float po, int srcTig, int parity) {
    float xe = __shfl_sync(FULLM, pe, srcTig, 4);
    float xo = __shfl_sync(FULLM, po, srcTig, 4);
    return parity ? xo : xe;
}

__global__ __launch_bounds__(256, 2) void attn_tc_kernel()
{
    __shared__ float SB[2 * STG_WORDS];   // K/V ring; aliased by epilogue
    __shared__ float sh_l[128];

    const int b   = blockIdx.z;
    const int h   = blockIdx.y;
    const int q0  = blockIdx.x * 128;
    const int tid = threadIdx.x;
    const int wid  = tid >> 5;
    const int lane = tid & 31;
    const int gid  = lane >> 2;
    const int tig  = lane & 3;
    const int wq   = wid >> 1;   // 0..3 : 32-row q group
    const int wn   = wid & 1;    // 0..1 : j/k half

    const float* qb = g_qkv + ((long)(b * 3 + 0) * HID + h * DHEAD) * N_POS;
    const float* kb = g_qkv + ((long)(b * 3 + 1) * HID + h * DHEAD) * N_POS;
    const float* vb = g_qkv + ((long)(b * 3 + 2) * HID + h * DHEAD) * N_POS;

    float* Ks0 = SB;
    float* Vs0 = SB + 32 * KS_STR;
    float* Ks1 = SB + STG_WORDS;
    float* Vs1 = SB + STG_WORDS + 32 * KS_STR;

    // ---- stage tiles 0 and 1 ----
    #pragma unroll
    for (int r = 0; r < 2; r++) {
        int c = tid + r * 256;
        int d = c >> 4, j4 = (c & 15) * 4;
        cp_async16(Ks0 + d * KS_STR + j4, kb + (long)d * N_POS + j4);
        cp_async16(Vs0 + d * VS_STR + j4, vb + (long)d * N_POS + j4);
    }
    asm volatile("cp.async.commit_group;\n" ::: "memory");
    #pragma unroll
    for (int r = 0; r < 2; r++) {
        int c = tid + r * 256;
        int d = c >> 4, j4 = (c & 15) * 4;
        cp_async16(Ks1 + d * KS_STR + j4, kb + (long)d * N_POS + 64 + j4);
        cp_async16(Vs1 + d * VS_STR + j4, vb + (long)d * N_POS + 64 + j4);
    }
    asm volatile("cp.async.commit_group;\n" ::: "memory");

    // ---- Q fragments in registers (one-time) ----
    uint32_t qf[2][4][4];
    #pragma unroll
    for (int mt = 0; mt < 2; mt++) {
        const int row = wq * 32 + mt * 16 + gid;
        const float* qp = qb + q0 + row;
        #pragma unroll
        for (int kk = 0; kk < 4; kk++) {
            qf[mt][kk][0] = f2tf(qp[(long)(kk * 8 + tig) * N_POS]);
            qf[mt][kk][1] = f2tf(qp[(long)(kk * 8 + tig) * N_POS + 8]);
            qf[mt][kk][2] = f2tf(qp[(long)(kk * 8 + tig + 4) * N_POS]);
            qf[mt][kk][3] = f2tf(qp[(long)(kk * 8 + tig + 4) * N_POS + 8]);
        }
    }
    if (tid < 128) sh_l[tid] = 0.0f;

    float O[2][4][4] = {};
    float l_lo[2] = {}, l_hi[2] = {};

    const int srcA = tig >> 1;
    const int srcB = srcA + 2;
    const int par  = tig & 1;

    for (int it = 0; it < N_POS / 64; it++) {
        const int s = it & 1;
        float* KsS = s ? Ks1 : Ks0;
        float* VsS = s ? Vs1 : Vs0;

        asm volatile("cp.async.wait_group 1;\n" ::: "memory");
        __syncthreads();   // tile it visible to all; also fences Q/sh_l init

        // ---- GEMM1: S[32q x 32j] = Q K' ----
        float S[2][4][4] = {};
        #pragma unroll
        for (int kk = 0; kk < 4; kk++) {
            const int c0 = kk * 8 + tig;
            #pragma unroll
            for (int nt = 0; nt < 4; nt++) {
                const int col = wn * 32 + nt * 8 + gid;
                uint32_t bb[2];
                bb[0] = f2tf(KsS[c0 * KS_STR + col]);
                bb[1] = f2tf(KsS[(c0 + 4) * KS_STR + col]);
                mma_tf32(S[0][nt], qf[0][kk], bb);
                mma_tf32(S[1][nt], qf[1][kk], bb);
            }
        }

        // ---- P = exp(10S - 10); accumulate l ----
        #pragma unroll
        for (int mt = 0; mt < 2; mt++)
            #pragma unroll
            for (int nt = 0; nt < 4; nt++) {
                S[mt][nt][0] = __expf(fmaf(S[mt][nt][0], SCALE, -SCALE));
                S[mt][nt][1] = __expf(fmaf(S[mt][nt][1], SCALE, -SCALE));
                S[mt][nt][2] = __expf(fmaf(S[mt][nt][2], SCALE, -SCALE));
                S[mt][nt][3] = __expf(fmaf(S[mt][nt][3], SCALE, -SCALE));
                l_lo[mt] += S[mt][nt][0] + S[mt][nt][1];
                l_hi[mt] += S[mt][nt][2] + S[mt][nt][3];
            }

        // ---- GEMM2: O += P V' (this warp's 32-k half) ----
        #pragma unroll
        for (int nt = 0; nt < 4; nt++) {
            uint32_t a0[4], a1[4];
            a0[0] = f2tf(quad_col(S[0][nt][0], S[0][nt][1], srcA, par));
            a0[1] = f2tf(quad_col(S[0][nt][2], S[0][nt][3], srcA, par));
            a0[2] = f2tf(quad_col(S[0][nt][0], S[0][nt][1], srcB, par));
            a0[3] = f2tf(quad_col(S[0][nt][2], S[0][nt][3], srcB, par));
            a1[0] = f2tf(quad_col(S[1][nt][0], S[1][nt][1], srcA, par));
            a1[1] = f2tf(quad_col(S[1][nt][2], S[1][nt][3], srcA, par));
            a1[2] = f2tf(quad_col(S[1][nt][0], S[1][nt][1], srcB, par));
            a1[3] = f2tf(quad_col(S[1][nt][2], S[1][nt][3], srcB, par));
            const int kbase = wn * 32 + nt * 8;
            #pragma unroll
            for (int dt = 0; dt < 4; dt++) {
                const int dcol = dt * 8 + gid;
                uint32_t bb[2];
                bb[0] = f2tf(VsS[dcol * VS_STR + kbase + tig]);
                bb[1] = f2tf(VsS[dcol * VS_STR + kbase + tig + 4]);
                mma_tf32(O[0][dt], a0, bb);
                mma_tf32(O[1][dt], a1, bb);
            }
        }

        __syncthreads();   // all warps done with this stage's smem

        // refill this stage with tile it+2 (or commit an empty group)
        if (it + 2 < N_POS / 64) {
            const int j0 = (it + 2) * 64;
            #pragma unroll
            for (int r = 0; r < 2; r++) {
                int c = tid + r * 256;
                int d = c >> 4, j4 = (c & 15) * 4;
                cp_async16(KsS + d * KS_STR + j4, kb + (long)d * N_POS + j0 + j4);
                cp_async16(VsS + d * VS_STR + j4, vb + (long)d * N_POS + j0 + j4);
            }
        }
        asm volatile("cp.async.commit_group;\n" ::: "memory");
    }

    // ---- reduce l ----
    #pragma unroll
    for (int mt = 0; mt < 2; mt++) {
        l_lo[mt] += __shfl_xor_sync(FULLM, l_lo[mt], 1);
        l_lo[mt] += __shfl_xor_sync(FULLM, l_lo[mt], 2);
        l_hi[mt] += __shfl_xor_sync(FULLM, l_hi[mt], 1);
        l_hi[mt] += __shfl_xor_sync(FULLM, l_hi[mt], 2);
        if (tig == 0) {
            atomicAdd(&sh_l[wq * 32 + mt * 16 + gid],     l_lo[mt]);
            atomicAdd(&sh_l[wq * 32 + mt * 16 + gid + 8], l_hi[mt]);
        }
    }
    __syncthreads();

    // ---- merge k-half partials via smem (aliases the K/V ring) ----
    float* Os = SB;                 // [32 d][OS_STR] (4352 words)
    float* PB = SB + 32 * OS_STR;   // [128 q][PB_STR] (4224 words)

    if (wn == 1) {
        #pragma unroll
        for (int mt = 0; mt < 2; mt++) {
            const int row = wq * 32 + mt * 16 + gid;
            #pragma unroll
            for (int nt = 0; nt < 4; nt++) {
                const int col = nt * 8 + 2 * tig;
                PB[row * PB_STR + col]           = O[mt][nt][0];
                PB[row * PB_STR + col + 1]       = O[mt][nt][1];
                PB[(row + 8) * PB_STR + col]     = O[mt][nt][2];
                PB[(row + 8) * PB_STR + col + 1] = O[mt][nt][3];
            }
        }
    }
    __syncthreads();
    if (wn == 0) {
        #pragma unroll
        for (int mt = 0; mt < 2; mt++) {
            const int row = wq * 32 + mt * 16 + gid;
            const float invl_lo = 1.0f / sh_l[row];
            const float invl_hi = 1.0f / sh_l[row + 8];
            #pragma unroll
            for (int nt = 0; nt < 4; nt++) {
                const int col = nt * 8 + 2 * tig;
                float o0 = (O[mt][nt][0] + PB[row * PB_STR + col])           * invl_lo;
                float o1 = (O[mt][nt][1] + PB[row * PB_STR + col + 1])       * invl_lo;
                float o2 = (O[mt][nt][2] + PB[(row + 8) * PB_STR + col])     * invl_hi;
                float o3 = (O[mt][nt][3] + PB[(row + 8) * PB_STR + col + 1]) * invl_hi;
                Os[col * OS_STR + row]           = o0;
                Os[(col + 1) * OS_STR + row]     = o1;
                Os[col * OS_STR + row + 8]       = o2;
                Os[(col + 1) * OS_STR + row + 8] = o3;
            }
        }
    }
    __syncthreads();

    float* ob = g_att + ((long)b * HID + h * DHEAD) * N_POS + q0;
    #pragma unroll
    for (int r = 0; r < 16; r++) {
        int idx = tid + r * 256;
        int d = idx >> 7, qi = idx & 127;
        ob[(long)d * N_POS + qi] = Os[d * OS_STR + qi];
    }
}

// ---------------------------------------------------------------------------
extern "C" void kernel_launch(void* const* d_in, const int* in_sizes, int n_in,
                              void* d_out, int out_size)
{
    const float* x     = (const float*)d_in[0];   // [4,256,64,64]
    const float* w_qkv = (const float*)d_in[1];   // [384,256]
    const float* w_out = (const float*)d_in[2];   // [256,128]
    const float* b_out = (const float*)d_in[3];   // [256]
    float* y = (float*)d_out;                     // [4,256,64,64]

    // A: qkv = w_qkv @ x   (tf32 split MMA)
    {
        dim3 grid(N_POS / 64, (3 * HID) / 64, BATCH);
        gemm_qkv_kernel<<<grid, 256>>>(w_qkv, x);
    }
    // B: L2-normalize q, k
    {
        int total = 2 * BATCH * HEADS * N_POS;
        norm_kernel<<<total / 256, 256>>>();
    }
    // C: tensor-core flash attention (q-tile 128)
    {
        dim3 grid(N_POS / 128, HEADS, BATCH);
        attn_tc_kernel<<<grid, 256>>>();
    }
    // D: y = w_out @ att + b_out   (tf32 split MMA)
    {
        dim3 grid(N_POS / 64, C_IN / 64, BATCH);
        gemm_out_kernel<<<grid, 256>>>(w_out, y, b_out);
    }
}